// round 12
// baseline (speedup 1.0000x reference)
#include <cuda_runtime.h>
#include <stdint.h>
#include <cuda_fp16.h>
#include <mma.h>
#include <math.h>

using namespace nvcuda;

#define T_TOK 8192
#define H_DIM 1024
#define I_DIM 512
#define E_NUM 8
#define MAXTILE 80

// ---------------- scratch (device globals; no allocations allowed) ----------
__device__ __align__(16) __half g_xs[T_TOK * H_DIM];      // permuted, rw-scaled
__device__ __align__(16) __half g_mid[T_TOK * I_DIM];     // u * silu(g)
__device__ __align__(16) __half g_wg[E_NUM * I_DIM * H_DIM];
__device__ __align__(16) __half g_wu[E_NUM * I_DIM * H_DIM];
__device__ __align__(16) __half g_wd[E_NUM * H_DIM * I_DIM];
__device__ int   g_tok[T_TOK];
__device__ int   g_pos[T_TOK];
__device__ int   g_sel[T_TOK];
__device__ float g_rw[T_TOK];
__device__ int   g_off[E_NUM + 1];
__device__ int   g_ntile;
__device__ int   g_te[MAXTILE];   // tile -> expert
__device__ int   g_tr[MAXTILE];   // tile -> row0 (permuted space)

// ---------------- cp.async helpers ------------------------------------------
__device__ __forceinline__ void cp16(unsigned dst, const void* src) {
    asm volatile("cp.async.cg.shared.global [%0], [%1], 16;\n" :: "r"(dst), "l"(src));
}
__device__ __forceinline__ void cp_commit() {
    asm volatile("cp.async.commit_group;\n");
}
template <int N> __device__ __forceinline__ void cp_wait() {
    asm volatile("cp.async.wait_group %0;\n" :: "n"(N));
}

// ---------------- K1: router (one warp per token, fp32 exact) ----------------
__global__ void router_kernel(const float* __restrict__ x,
                              const float* __restrict__ gate_w) {
    int warp = (blockIdx.x * blockDim.x + threadIdx.x) >> 5;
    int lane = threadIdx.x & 31;
    if (warp >= T_TOK) return;
    const float* xr = x + (size_t)warp * H_DIM;
    float xv[32];
#pragma unroll
    for (int i = 0; i < 32; i++) xv[i] = xr[lane + i * 32];

    float best = -1e30f;
    int bsel = 0;
#pragma unroll
    for (int e = 0; e < E_NUM; e++) {
        const float* gw = gate_w + e * H_DIM;
        float s = 0.f;
#pragma unroll
        for (int i = 0; i < 32; i++) s += xv[i] * gw[lane + i * 32];
#pragma unroll
        for (int o = 16; o > 0; o >>= 1) s += __shfl_xor_sync(0xffffffffu, s, o);
        if (s > best) { best = s; bsel = e; }
    }
    if (lane == 0) {
        g_sel[warp] = bsel;
        g_rw[warp] = 1.f / (1.f + expf(-best));
    }
}

// ---------------- K2: count + prefix + assign + tile table -------------------
__global__ __launch_bounds__(1024) void route_finish_kernel() {
    __shared__ int scnt[E_NUM];
    __shared__ int sfill[E_NUM];
    int tid = threadIdx.x;
    if (tid < E_NUM) scnt[tid] = 0;
    __syncthreads();
    for (int i = tid; i < T_TOK; i += 1024) atomicAdd(&scnt[g_sel[i]], 1);
    __syncthreads();
    if (tid == 0) {
        int acc = 0, nt = 0;
        for (int e = 0; e < E_NUM; e++) {
            g_off[e] = acc;
            sfill[e] = acc;
            acc += scnt[e];
        }
        g_off[E_NUM] = acc;
        for (int e = 0; e < E_NUM; e++)
            for (int r0 = g_off[e]; r0 < g_off[e + 1]; r0 += 128) {
                g_te[nt] = e; g_tr[nt] = r0; nt++;
            }
        g_ntile = nt;
    }
    __syncthreads();
    for (int i = tid; i < T_TOK; i += 1024) {
        int p = atomicAdd(&sfill[g_sel[i]], 1);
        g_tok[p] = i;
        g_pos[i] = p;
    }
}

// ---------------- K3: fused weight-convert + input-scatter -------------------
#define PREP_B 1408
__global__ void prep_copy_kernel(const float* __restrict__ x,
                                 const float* __restrict__ wg,
                                 const float* __restrict__ wu,
                                 const float* __restrict__ wd) {
    if (blockIdx.x < PREP_B) {
        const int N4 = (E_NUM * I_DIM * H_DIM) / 4;
        int i = blockIdx.x * blockDim.x + threadIdx.x;
        int stride = PREP_B * blockDim.x;
        for (; i < N4; i += stride) {
            float4 a = ((const float4*)wg)[i];
            ((__half2*)g_wg)[i * 2]     = __floats2half2_rn(a.x, a.y);
            ((__half2*)g_wg)[i * 2 + 1] = __floats2half2_rn(a.z, a.w);
            float4 b = ((const float4*)wu)[i];
            ((__half2*)g_wu)[i * 2]     = __floats2half2_rn(b.x, b.y);
            ((__half2*)g_wu)[i * 2 + 1] = __floats2half2_rn(b.z, b.w);
            float4 c = ((const float4*)wd)[i];
            ((__half2*)g_wd)[i * 2]     = __floats2half2_rn(c.x, c.y);
            ((__half2*)g_wd)[i * 2 + 1] = __floats2half2_rn(c.z, c.w);
        }
    } else {
        const int TOTAL = T_TOK * (H_DIM / 4);
        int i = (blockIdx.x - PREP_B) * blockDim.x + threadIdx.x;
        int stride = (2048 - PREP_B) * blockDim.x;
        for (; i < TOTAL; i += stride) {
            int t = i >> 8;
            int j = i & 255;
            int p = g_pos[t];
            float rw = g_rw[t];
            float4 v = ((const float4*)(x + (size_t)t * H_DIM))[j];
            __half2 lo = __floats2half2_rn(v.x * rw, v.y * rw);
            __half2 hi = __floats2half2_rn(v.z * rw, v.w * rw);
            ((__half2*)(g_xs + (size_t)p * H_DIM))[j * 2]     = lo;
            ((__half2*)(g_xs + (size_t)p * H_DIM))[j * 2 + 1] = hi;
        }
    }
}

// ---------------- K4: grouped GEMM1 fp16 (gate & up fused) + silu ------------
// Tile table driven. Block tile 128(M) x 64(N), BK=64, 2-stage pipeline.
#define SP 72                       /* smem row stride in halves */
#define G1_STG_H ((128 + 64 + 64) * SP)   /* 18432 halves = 36864 B */
__global__ __launch_bounds__(256) void gemm1_kernel() {
    extern __shared__ __half sm[];
    int ty = blockIdx.y;
    if (ty >= g_ntile) return;
    int e = g_te[ty];
    int row0 = g_tr[ty];
    int pe = g_off[e + 1];
    int i0 = blockIdx.x * 64;

    int tid = threadIdx.x;
    int wid = tid >> 5;
    int wm = wid >> 1, wn = wid & 1;

    unsigned sb = (unsigned)__cvta_generic_to_shared(sm);
    const __half* wgb = g_wg + ((size_t)e * I_DIM + i0) * H_DIM;
    const __half* wub = g_wu + ((size_t)e * I_DIM + i0) * H_DIM;

    // hoisted per-thread load descriptors (row/col fixed; only k advances)
    const __half* asrc[4]; unsigned adst[4];
#pragma unroll
    for (int it = 0; it < 4; it++) {
        int idx = tid + it * 256;
        int r = idx >> 3, c = idx & 7;
        int gr = row0 + r; if (gr > pe - 1) gr = pe - 1;
        asrc[it] = g_xs + (size_t)gr * H_DIM + c * 8;
        adst[it] = (r * SP + c * 8) * 2;
    }
    const __half* wgsrc[2]; const __half* wusrc[2]; unsigned wdst[2];
#pragma unroll
    for (int it = 0; it < 2; it++) {
        int idx = tid + it * 256;
        int r = idx >> 3, c = idx & 7;
        wgsrc[it] = wgb + (size_t)r * H_DIM + c * 8;
        wusrc[it] = wub + (size_t)r * H_DIM + c * 8;
        wdst[it]  = (r * SP + c * 8) * 2;
    }

    wmma::fragment<wmma::accumulator, 16, 16, 16, float> cg[2][2], cu[2][2];
#pragma unroll
    for (int mm = 0; mm < 2; mm++)
#pragma unroll
        for (int nn = 0; nn < 2; nn++) {
            wmma::fill_fragment(cg[mm][nn], 0.f);
            wmma::fill_fragment(cu[mm][nn], 0.f);
        }

    auto issue = [&](int kt, int s) {
        int k0 = kt * 64;
        unsigned base = sb + s * G1_STG_H * 2;
        unsigned wbg = base + 128 * SP * 2;
        unsigned wbu = wbg + 64 * SP * 2;
#pragma unroll
        for (int it = 0; it < 4; it++) cp16(base + adst[it], asrc[it] + k0);
#pragma unroll
        for (int it = 0; it < 2; it++) {
            cp16(wbg + wdst[it], wgsrc[it] + k0);
            cp16(wbu + wdst[it], wusrc[it] + k0);
        }
        cp_commit();
    };

    issue(0, 0);
    const int KT = H_DIM / 64;
    for (int kt = 0; kt < KT; kt++) {
        int s = kt & 1;
        if (kt + 1 < KT) { issue(kt + 1, s ^ 1); cp_wait<1>(); }
        else             { cp_wait<0>(); }
        __syncthreads();

        __half* As  = sm + s * G1_STG_H;
        __half* Wgs = As + 128 * SP;
        __half* Wus = Wgs + 64 * SP;
#pragma unroll
        for (int ks = 0; ks < 4; ks++) {
            wmma::fragment<wmma::matrix_a, 16, 16, 16, __half, wmma::row_major> a[2];
            wmma::fragment<wmma::matrix_b, 16, 16, 16, __half, wmma::col_major> bg[2], bu[2];
#pragma unroll
            for (int mm = 0; mm < 2; mm++)
                wmma::load_matrix_sync(a[mm], As + (wm * 32 + mm * 16) * SP + ks * 16, SP);
#pragma unroll
            for (int nn = 0; nn < 2; nn++) {
                wmma::load_matrix_sync(bg[nn], Wgs + (wn * 32 + nn * 16) * SP + ks * 16, SP);
                wmma::load_matrix_sync(bu[nn], Wus + (wn * 32 + nn * 16) * SP + ks * 16, SP);
            }
#pragma unroll
            for (int mm = 0; mm < 2; mm++)
#pragma unroll
                for (int nn = 0; nn < 2; nn++) {
                    wmma::mma_sync(cg[mm][nn], a[mm], bg[nn], cg[mm][nn]);
                    wmma::mma_sync(cu[mm][nn], a[mm], bu[nn], cu[mm][nn]);
                }
        }
        __syncthreads();
    }

    // SwiGLU in registers -> float smem -> fp16 g_mid
    float* Epi = (float*)sm;                     // 128 x 72 floats = 36864 B
#pragma unroll
    for (int mm = 0; mm < 2; mm++)
#pragma unroll
        for (int nn = 0; nn < 2; nn++) {
            wmma::fragment<wmma::accumulator, 16, 16, 16, float> t;
#pragma unroll
            for (int i = 0; i < t.num_elements; i++) {
                float g = cg[mm][nn].x[i];
                t.x[i] = cu[mm][nn].x[i] * g / (1.f + expf(-g));
            }
            wmma::store_matrix_sync(Epi + (wm * 32 + mm * 16) * SP + wn * 32 + nn * 16,
                                    t, SP, wmma::mem_row_major);
        }
    __syncthreads();

    for (int idx = tid; idx < 128 * 8; idx += 256) {     // 8 halves per item
        int r = idx >> 3, c8 = idx & 7;
        int p = row0 + r;
        if (p < pe) {
            const float* src = Epi + r * SP + c8 * 8;
            __half2 h[4];
#pragma unroll
            for (int q = 0; q < 4; q++) h[q] = __floats2half2_rn(src[q * 2], src[q * 2 + 1]);
            *(uint4*)(g_mid + (size_t)p * I_DIM + i0 + c8 * 8) = *(uint4*)h;
        }
    }
}

// ---------------- K5: grouped GEMM2 fp16 (down) + scatter to output ----------
// Tile table driven. Block tile 128(M) x 64(N), BK=64, K=512.
#define G2_STG_H ((128 + 64) * SP)               /* 13824 halves = 27648 B */
__global__ __launch_bounds__(256) void gemm2_kernel(float* __restrict__ out) {
    extern __shared__ __half sm[];
    int ty = blockIdx.y;
    if (ty >= g_ntile) return;
    int e = g_te[ty];
    int row0 = g_tr[ty];
    int pe = g_off[e + 1];
    int n0 = blockIdx.x * 64;

    int tid = threadIdx.x;
    int wid = tid >> 5;
    int wm = wid >> 1, wn = wid & 1;

    unsigned sb = (unsigned)__cvta_generic_to_shared(sm);
    const __half* wdb = g_wd + ((size_t)e * H_DIM + n0) * I_DIM;

    const __half* asrc[4]; unsigned adst[4];
#pragma unroll
    for (int it = 0; it < 4; it++) {
        int idx = tid + it * 256;
        int r = idx >> 3, c = idx & 7;
        int gr = row0 + r; if (gr > pe - 1) gr = pe - 1;
        asrc[it] = g_mid + (size_t)gr * I_DIM + c * 8;
        adst[it] = (r * SP + c * 8) * 2;
    }
    const __half* wsrc[2]; unsigned wdst[2];
#pragma unroll
    for (int it = 0; it < 2; it++) {
        int idx = tid + it * 256;
        int r = idx >> 3, c = idx & 7;
        wsrc[it] = wdb + (size_t)r * I_DIM + c * 8;
        wdst[it] = (r * SP + c * 8) * 2;
    }

    wmma::fragment<wmma::accumulator, 16, 16, 16, float> c[2][2];
#pragma unroll
    for (int mm = 0; mm < 2; mm++)
#pragma unroll
        for (int nn = 0; nn < 2; nn++) wmma::fill_fragment(c[mm][nn], 0.f);

    auto issue = [&](int kt, int s) {
        int k0 = kt * 64;
        unsigned base = sb + s * G2_STG_H * 2;
        unsigned wb = base + 128 * SP * 2;
#pragma unroll
        for (int it = 0; it < 4; it++) cp16(base + adst[it], asrc[it] + k0);
#pragma unroll
        for (int it = 0; it < 2; it++) cp16(wb + wdst[it], wsrc[it] + k0);
        cp_commit();
    };

    issue(0, 0);
    const int KT = I_DIM / 64;
    for (int kt = 0; kt < KT; kt++) {
        int s = kt & 1;
        if (kt + 1 < KT) { issue(kt + 1, s ^ 1); cp_wait<1>(); }
        else             { cp_wait<0>(); }
        __syncthreads();

        __half* As = sm + s * G2_STG_H;
        __half* Ws = As + 128 * SP;
#pragma unroll
        for (int ks = 0; ks < 4; ks++) {
            wmma::fragment<wmma::matrix_a, 16, 16, 16, __half, wmma::row_major> a[2];
            wmma::fragment<wmma::matrix_b, 16, 16, 16, __half, wmma::col_major> b[2];
#pragma unroll
            for (int mm = 0; mm < 2; mm++)
                wmma::load_matrix_sync(a[mm], As + (wm * 32 + mm * 16) * SP + ks * 16, SP);
#pragma unroll
            for (int nn = 0; nn < 2; nn++)
                wmma::load_matrix_sync(b[nn], Ws + (wn * 32 + nn * 16) * SP + ks * 16, SP);
#pragma unroll
            for (int mm = 0; mm < 2; mm++)
#pragma unroll
                for (int nn = 0; nn < 2; nn++)
                    wmma::mma_sync(c[mm][nn], a[mm], b[nn], c[mm][nn]);
        }
        __syncthreads();
    }

    float* Epi = (float*)sm;                     // 128 x 72 floats
#pragma unroll
    for (int mm = 0; mm < 2; mm++)
#pragma unroll
        for (int nn = 0; nn < 2; nn++)
            wmma::store_matrix_sync(Epi + (wm * 32 + mm * 16) * SP + wn * 32 + nn * 16,
                                    c[mm][nn], SP, wmma::mem_row_major);
    __syncthreads();

    for (int idx = tid; idx < 128 * 16; idx += 256) {    // float4 per item
        int r = idx >> 4, c4 = idx & 15;
        int p = row0 + r;
        if (p < pe) {
            int t = g_tok[p];
            float4 v = *(const float4*)(Epi + r * SP + c4 * 4);
            *(float4*)(out + (size_t)t * H_DIM + n0 + c4 * 4) = v;
        }
    }
}

// ---------------- launch ------------------------------------------------------
extern "C" void kernel_launch(void* const* d_in, const int* in_sizes, int n_in,
                              void* d_out, int out_size) {
    const float* x      = (const float*)d_in[0];
    const float* gate_w = (const float*)d_in[1];
    const float* w_gate = (const float*)d_in[2];
    const float* w_up   = (const float*)d_in[3];
    const float* w_down = (const float*)d_in[4];
    float* out = (float*)d_out;

    const int SM1 = 2 * G1_STG_H * 2;   // 73728 B
    const int SM2 = 2 * G2_STG_H * 2;   // 55296 B
    cudaFuncSetAttribute(gemm1_kernel, cudaFuncAttributeMaxDynamicSharedMemorySize, SM1);
    cudaFuncSetAttribute(gemm2_kernel, cudaFuncAttributeMaxDynamicSharedMemorySize, SM2);

    // max M-tiles across experts: 8192/128 full + <=8 partial = 72
    const int YT = T_TOK / 128 + E_NUM;  // 72

    router_kernel<<<T_TOK / 8, 256>>>(x, gate_w);
    route_finish_kernel<<<1, 1024>>>();
    prep_copy_kernel<<<2048, 256>>>(x, w_gate, w_up, w_down);
    gemm1_kernel<<<dim3(I_DIM / 64, YT), 256, SM1>>>();
    gemm2_kernel<<<dim3(H_DIM / 64, YT), 256, SM2>>>(out);
}

// round 13
// speedup vs baseline: 1.4104x; 1.4104x over previous
#include <cuda_runtime.h>
#include <stdint.h>
#include <cuda_fp16.h>
#include <mma.h>
#include <math.h>

using namespace nvcuda;

#define T_TOK 8192
#define H_DIM 1024
#define I_DIM 512
#define E_NUM 8

// ---------------- scratch (device globals; no allocations allowed) ----------
__device__ __align__(16) __half g_xs[T_TOK * H_DIM];      // permuted, rw-scaled
__device__ __align__(16) __half g_mid[T_TOK * I_DIM];     // u * silu(g)
__device__ __align__(16) __half g_wg[E_NUM * I_DIM * H_DIM];
__device__ __align__(16) __half g_wu[E_NUM * I_DIM * H_DIM];
__device__ __align__(16) __half g_wd[E_NUM * H_DIM * I_DIM];
__device__ int   g_tok[T_TOK];
__device__ int   g_pos[T_TOK];
__device__ int   g_sel[T_TOK];
__device__ float g_rw[T_TOK];
__device__ int   g_off[E_NUM + 1];

// ---------------- cp.async helpers ------------------------------------------
__device__ __forceinline__ void cp16(unsigned dst, const void* src) {
    asm volatile("cp.async.cg.shared.global [%0], [%1], 16;\n" :: "r"(dst), "l"(src));
}
__device__ __forceinline__ void cp_commit() {
    asm volatile("cp.async.commit_group;\n");
}
template <int N> __device__ __forceinline__ void cp_wait() {
    asm volatile("cp.async.wait_group %0;\n" :: "n"(N));
}

// ---------------- K1: router (one warp per token, fp32 exact) ----------------
__global__ void router_kernel(const float* __restrict__ x,
                              const float* __restrict__ gate_w) {
    int warp = (blockIdx.x * blockDim.x + threadIdx.x) >> 5;
    int lane = threadIdx.x & 31;
    if (warp >= T_TOK) return;
    const float* xr = x + (size_t)warp * H_DIM;
    float xv[32];
#pragma unroll
    for (int i = 0; i < 32; i++) xv[i] = xr[lane + i * 32];

    float best = -1e30f;
    int bsel = 0;
#pragma unroll
    for (int e = 0; e < E_NUM; e++) {
        const float* gw = gate_w + e * H_DIM;
        float s = 0.f;
#pragma unroll
        for (int i = 0; i < 32; i++) s += xv[i] * gw[lane + i * 32];
#pragma unroll
        for (int o = 16; o > 0; o >>= 1) s += __shfl_xor_sync(0xffffffffu, s, o);
        if (s > best) { best = s; bsel = e; }
    }
    if (lane == 0) {
        g_sel[warp] = bsel;
        g_rw[warp] = 1.f / (1.f + expf(-best));
    }
}

// ---------------- K2: count + prefix + assign (single block) -----------------
__global__ __launch_bounds__(1024) void route_finish_kernel() {
    __shared__ int scnt[E_NUM];
    __shared__ int sfill[E_NUM];
    int tid = threadIdx.x;
    if (tid < E_NUM) scnt[tid] = 0;
    __syncthreads();
    for (int i = tid; i < T_TOK; i += 1024) atomicAdd(&scnt[g_sel[i]], 1);
    __syncthreads();
    if (tid == 0) {
        int acc = 0;
        for (int e = 0; e < E_NUM; e++) {
            g_off[e] = acc;
            sfill[e] = acc;
            acc += scnt[e];
        }
        g_off[E_NUM] = acc;
    }
    __syncthreads();
    for (int i = tid; i < T_TOK; i += 1024) {
        int p = atomicAdd(&sfill[g_sel[i]], 1);
        g_tok[p] = i;
        g_pos[i] = p;
    }
}

// ---------------- K3: fused weight-convert + input-scatter -------------------
#define PREP_B 1408
__global__ void prep_copy_kernel(const float* __restrict__ x,
                                 const float* __restrict__ wg,
                                 const float* __restrict__ wu,
                                 const float* __restrict__ wd) {
    if (blockIdx.x < PREP_B) {
        const int N4 = (E_NUM * I_DIM * H_DIM) / 4;
        int i = blockIdx.x * blockDim.x + threadIdx.x;
        int stride = PREP_B * blockDim.x;
        for (; i < N4; i += stride) {
            float4 a = ((const float4*)wg)[i];
            ((__half2*)g_wg)[i * 2]     = __floats2half2_rn(a.x, a.y);
            ((__half2*)g_wg)[i * 2 + 1] = __floats2half2_rn(a.z, a.w);
            float4 b = ((const float4*)wu)[i];
            ((__half2*)g_wu)[i * 2]     = __floats2half2_rn(b.x, b.y);
            ((__half2*)g_wu)[i * 2 + 1] = __floats2half2_rn(b.z, b.w);
            float4 c = ((const float4*)wd)[i];
            ((__half2*)g_wd)[i * 2]     = __floats2half2_rn(c.x, c.y);
            ((__half2*)g_wd)[i * 2 + 1] = __floats2half2_rn(c.z, c.w);
        }
    } else {
        const int TOTAL = T_TOK * (H_DIM / 4);
        int i = (blockIdx.x - PREP_B) * blockDim.x + threadIdx.x;
        int stride = (2048 - PREP_B) * blockDim.x;
        for (; i < TOTAL; i += stride) {
            int t = i >> 8;
            int j = i & 255;
            int p = g_pos[t];
            float rw = g_rw[t];
            float4 v = ((const float4*)(x + (size_t)t * H_DIM))[j];
            __half2 lo = __floats2half2_rn(v.x * rw, v.y * rw);
            __half2 hi = __floats2half2_rn(v.z * rw, v.w * rw);
            ((__half2*)(g_xs + (size_t)p * H_DIM))[j * 2]     = lo;
            ((__half2*)(g_xs + (size_t)p * H_DIM))[j * 2 + 1] = hi;
        }
    }
}

// ---------------- K4: grouped GEMM1 fp16 (gate & up fused) + silu ------------
// Block tile 128(M) x 64(N), BK=64, 2-stage cp.async double buffer.
// 8 warps in 4x2 grid; warp tile 32x32, gate & up accumulators in registers.
#define SP 72                       /* smem row stride in halves */
#define G1_STG_H ((128 + 64 + 64) * SP)   /* 18432 halves = 36864 B */
__global__ __launch_bounds__(256) void gemm1_kernel() {
    extern __shared__ __half sm[];
    int e = blockIdx.z;
    int ps = g_off[e], pe = g_off[e + 1];
    int row0 = ps + blockIdx.y * 128;
    if (row0 >= pe) return;
    int i0 = blockIdx.x * 64;

    int tid = threadIdx.x;
    int wid = tid >> 5;
    int wm = wid >> 1, wn = wid & 1;

    unsigned sb = (unsigned)__cvta_generic_to_shared(sm);
    const __half* wgb = g_wg + ((size_t)e * I_DIM + i0) * H_DIM;
    const __half* wub = g_wu + ((size_t)e * I_DIM + i0) * H_DIM;

    wmma::fragment<wmma::accumulator, 16, 16, 16, float> cg[2][2], cu[2][2];
#pragma unroll
    for (int mm = 0; mm < 2; mm++)
#pragma unroll
        for (int nn = 0; nn < 2; nn++) {
            wmma::fill_fragment(cg[mm][nn], 0.f);
            wmma::fill_fragment(cu[mm][nn], 0.f);
        }

    auto issue = [&](int kt, int s) {
        int k0 = kt * 64;
        unsigned As = sb + s * G1_STG_H * 2;
        unsigned Wg = As + 128 * SP * 2;
        unsigned Wu = Wg + 64 * SP * 2;
#pragma unroll
        for (int it = 0; it < 4; it++) {                    // A: 128 x 64 halves
            int idx = tid + it * 256;
            int r = idx >> 3, c = idx & 7;
            int gr = row0 + r; if (gr > pe - 1) gr = pe - 1;
            cp16(As + (r * SP + c * 8) * 2, g_xs + (size_t)gr * H_DIM + k0 + c * 8);
        }
#pragma unroll
        for (int it = 0; it < 2; it++) {                    // Wg, Wu: 64 x 64
            int idx = tid + it * 256;
            int r = idx >> 3, c = idx & 7;
            cp16(Wg + (r * SP + c * 8) * 2, wgb + (size_t)r * H_DIM + k0 + c * 8);
            cp16(Wu + (r * SP + c * 8) * 2, wub + (size_t)r * H_DIM + k0 + c * 8);
        }
        cp_commit();
    };

    issue(0, 0);
    const int KT = H_DIM / 64;
    for (int kt = 0; kt < KT; kt++) {
        int s = kt & 1;
        if (kt + 1 < KT) { issue(kt + 1, s ^ 1); cp_wait<1>(); }
        else             { cp_wait<0>(); }
        __syncthreads();

        __half* As  = sm + s * G1_STG_H;
        __half* Wgs = As + 128 * SP;
        __half* Wus = Wgs + 64 * SP;
#pragma unroll
        for (int ks = 0; ks < 4; ks++) {
            wmma::fragment<wmma::matrix_a, 16, 16, 16, __half, wmma::row_major> a[2];
            wmma::fragment<wmma::matrix_b, 16, 16, 16, __half, wmma::col_major> bg[2], bu[2];
#pragma unroll
            for (int mm = 0; mm < 2; mm++)
                wmma::load_matrix_sync(a[mm], As + (wm * 32 + mm * 16) * SP + ks * 16, SP);
#pragma unroll
            for (int nn = 0; nn < 2; nn++) {
                wmma::load_matrix_sync(bg[nn], Wgs + (wn * 32 + nn * 16) * SP + ks * 16, SP);
                wmma::load_matrix_sync(bu[nn], Wus + (wn * 32 + nn * 16) * SP + ks * 16, SP);
            }
#pragma unroll
            for (int mm = 0; mm < 2; mm++)
#pragma unroll
                for (int nn = 0; nn < 2; nn++) {
                    wmma::mma_sync(cg[mm][nn], a[mm], bg[nn], cg[mm][nn]);
                    wmma::mma_sync(cu[mm][nn], a[mm], bu[nn], cu[mm][nn]);
                }
        }
        __syncthreads();
    }

    // SwiGLU in registers -> float smem -> fp16 g_mid
    float* Epi = (float*)sm;                     // 128 x 72 floats = 36864 B
#pragma unroll
    for (int mm = 0; mm < 2; mm++)
#pragma unroll
        for (int nn = 0; nn < 2; nn++) {
            wmma::fragment<wmma::accumulator, 16, 16, 16, float> t;
#pragma unroll
            for (int i = 0; i < t.num_elements; i++) {
                float g = cg[mm][nn].x[i];
                t.x[i] = cu[mm][nn].x[i] * g / (1.f + expf(-g));
            }
            wmma::store_matrix_sync(Epi + (wm * 32 + mm * 16) * SP + wn * 32 + nn * 16,
                                    t, SP, wmma::mem_row_major);
        }
    __syncthreads();

    for (int idx = tid; idx < 128 * 8; idx += 256) {     // 8 halves per item
        int r = idx >> 3, c8 = idx & 7;
        int p = row0 + r;
        if (p < pe) {
            const float* src = Epi + r * SP + c8 * 8;
            __half2 h[4];
#pragma unroll
            for (int q = 0; q < 4; q++) h[q] = __floats2half2_rn(src[q * 2], src[q * 2 + 1]);
            *(uint4*)(g_mid + (size_t)p * I_DIM + i0 + c8 * 8) = *(uint4*)h;
        }
    }
}

// ---------------- K5: grouped GEMM2 fp16 (down) + scatter to output ----------
// Block tile 128(M) x 128(N), BK=64, K=512, 2-stage pipeline.
// 8 warps in 2x4 grid; warp tile 64x32 -> LDSM ratio 10.67 MAC/B (was 8.2).
#define G2_STG_H ((128 + 128) * SP)              /* 18432 halves = 36864 B */
#define EPS 132                                  /* epilogue fp32 row stride */
__global__ __launch_bounds__(256) void gemm2_kernel(float* __restrict__ out) {
    extern __shared__ __half sm[];
    int e = blockIdx.z;
    int ps = g_off[e], pe = g_off[e + 1];
    int row0 = ps + blockIdx.y * 128;
    if (row0 >= pe) return;
    int n0 = blockIdx.x * 128;

    int tid = threadIdx.x;
    int wid = tid >> 5;
    int wm = wid >> 2, wn = wid & 3;             // 2x4 warp grid, tile 64x32

    unsigned sb = (unsigned)__cvta_generic_to_shared(sm);
    const __half* wdb = g_wd + ((size_t)e * H_DIM + n0) * I_DIM;

    wmma::fragment<wmma::accumulator, 16, 16, 16, float> c[4][2];
#pragma unroll
    for (int mm = 0; mm < 4; mm++)
#pragma unroll
        for (int nn = 0; nn < 2; nn++) wmma::fill_fragment(c[mm][nn], 0.f);

    auto issue = [&](int kt, int s) {
        int k0 = kt * 64;
        unsigned As = sb + s * G2_STG_H * 2;
        unsigned Ws = As + 128 * SP * 2;
#pragma unroll
        for (int it = 0; it < 4; it++) {                    // A: 128 x 64 halves
            int idx = tid + it * 256;
            int r = idx >> 3, cc = idx & 7;
            int gr = row0 + r; if (gr > pe - 1) gr = pe - 1;
            cp16(As + (r * SP + cc * 8) * 2, g_mid + (size_t)gr * I_DIM + k0 + cc * 8);
        }
#pragma unroll
        for (int it = 0; it < 4; it++) {                    // W: 128 x 64 halves
            int idx = tid + it * 256;
            int r = idx >> 3, cc = idx & 7;
            cp16(Ws + (r * SP + cc * 8) * 2, wdb + (size_t)r * I_DIM + k0 + cc * 8);
        }
        cp_commit();
    };

    issue(0, 0);
    const int KT = I_DIM / 64;
    for (int kt = 0; kt < KT; kt++) {
        int s = kt & 1;
        if (kt + 1 < KT) { issue(kt + 1, s ^ 1); cp_wait<1>(); }
        else             { cp_wait<0>(); }
        __syncthreads();

        __half* As = sm + s * G2_STG_H;
        __half* Ws = As + 128 * SP;
#pragma unroll
        for (int ks = 0; ks < 4; ks++) {
            wmma::fragment<wmma::matrix_a, 16, 16, 16, __half, wmma::row_major> a[4];
            wmma::fragment<wmma::matrix_b, 16, 16, 16, __half, wmma::col_major> b[2];
#pragma unroll
            for (int mm = 0; mm < 4; mm++)
                wmma::load_matrix_sync(a[mm], As + (wm * 64 + mm * 16) * SP + ks * 16, SP);
#pragma unroll
            for (int nn = 0; nn < 2; nn++)
                wmma::load_matrix_sync(b[nn], Ws + (wn * 32 + nn * 16) * SP + ks * 16, SP);
#pragma unroll
            for (int mm = 0; mm < 4; mm++)
#pragma unroll
                for (int nn = 0; nn < 2; nn++)
                    wmma::mma_sync(c[mm][nn], a[mm], b[nn], c[mm][nn]);
        }
        __syncthreads();
    }

    float* Epi = (float*)sm;                     // 128 x 132 floats = 67584 B
#pragma unroll
    for (int mm = 0; mm < 4; mm++)
#pragma unroll
        for (int nn = 0; nn < 2; nn++)
            wmma::store_matrix_sync(Epi + (wm * 64 + mm * 16) * EPS + wn * 32 + nn * 16,
                                    c[mm][nn], EPS, wmma::mem_row_major);
    __syncthreads();

    for (int idx = tid; idx < 128 * 32; idx += 256) {    // float4 per item
        int r = idx >> 5, c4 = idx & 31;
        int p = row0 + r;
        if (p < pe) {
            int t = g_tok[p];
            float4 v = *(const float4*)(Epi + r * EPS + c4 * 4);
            *(float4*)(out + (size_t)t * H_DIM + n0 + c4 * 4) = v;
        }
    }
}

// ---------------- launch ------------------------------------------------------
extern "C" void kernel_launch(void* const* d_in, const int* in_sizes, int n_in,
                              void* d_out, int out_size) {
    const float* x      = (const float*)d_in[0];
    const float* gate_w = (const float*)d_in[1];
    const float* w_gate = (const float*)d_in[2];
    const float* w_up   = (const float*)d_in[3];
    const float* w_down = (const float*)d_in[4];
    float* out = (float*)d_out;

    const int SM1 = 2 * G1_STG_H * 2;   // 73728 B
    const int SM2 = 2 * G2_STG_H * 2;   // 73728 B (epilogue 67584 B fits)
    cudaFuncSetAttribute(gemm1_kernel, cudaFuncAttributeMaxDynamicSharedMemorySize, SM1);
    cudaFuncSetAttribute(gemm2_kernel, cudaFuncAttributeMaxDynamicSharedMemorySize, SM2);

    router_kernel<<<T_TOK / 8, 256>>>(x, gate_w);
    route_finish_kernel<<<1, 1024>>>();
    prep_copy_kernel<<<2048, 256>>>(x, w_gate, w_up, w_down);
    gemm1_kernel<<<dim3(I_DIM / 64, T_TOK / 128, E_NUM), 256, SM1>>>();
    gemm2_kernel<<<dim3(H_DIM / 128, T_TOK / 128, E_NUM), 256, SM2>>>(out);
}

// round 15
// speedup vs baseline: 1.5623x; 1.1077x over previous
#include <cuda_runtime.h>
#include <stdint.h>
#include <cuda_fp16.h>
#include <mma.h>
#include <math.h>

using namespace nvcuda;

#define T_TOK 8192
#define H_DIM 1024
#define I_DIM 512
#define E_NUM 8

// ---------------- scratch (device globals; no allocations allowed) ----------
__device__ __align__(16) __half g_xs[T_TOK * H_DIM];      // permuted, rw-scaled
__device__ __align__(16) __half g_mid[T_TOK * I_DIM];     // u * silu(g)
__device__ __align__(16) __half g_wg[E_NUM * I_DIM * H_DIM];
__device__ __align__(16) __half g_wu[E_NUM * I_DIM * H_DIM];
__device__ __align__(16) __half g_wd[E_NUM * H_DIM * I_DIM];
__device__ int   g_tok[T_TOK];
__device__ int   g_pos[T_TOK];
__device__ int   g_sel[T_TOK];
__device__ float g_rw[T_TOK];
__device__ int   g_off[E_NUM + 1];

// ---------------- cp.async helpers ------------------------------------------
__device__ __forceinline__ void cp16(unsigned dst, const void* src) {
    asm volatile("cp.async.cg.shared.global [%0], [%1], 16;\n" :: "r"(dst), "l"(src));
}
__device__ __forceinline__ void cp_commit() {
    asm volatile("cp.async.commit_group;\n");
}
template <int N> __device__ __forceinline__ void cp_wait() {
    asm volatile("cp.async.wait_group %0;\n" :: "n"(N));
}

// ---------------- K1: FUSED router + weight fp32->fp16 conversion ------------
// Blocks [0, 1024): router, one warp per token, gate_w staged in smem.
// Blocks [1024, 3072): weight conversion (independent of routing -> overlaps).
#define RT_B 1024
#define FUSE_B 3072
__global__ __launch_bounds__(256) void fused_router_prep_kernel(
    const float* __restrict__ x, const float* __restrict__ gate_w,
    const float* __restrict__ wg, const float* __restrict__ wu,
    const float* __restrict__ wd) {
    if (blockIdx.x < RT_B) {
        __shared__ float sgw[E_NUM * H_DIM];          // 32 KB
        int tid = threadIdx.x;
        // cooperative load of gate_w (2048 float4)
        for (int i = tid; i < (E_NUM * H_DIM) / 4; i += 256)
            ((float4*)sgw)[i] = ((const float4*)gate_w)[i];
        __syncthreads();

        int token = blockIdx.x * 8 + (tid >> 5);
        int lane = tid & 31;
        const float* xr = x + (size_t)token * H_DIM;
        float xv[32];
#pragma unroll
        for (int i = 0; i < 32; i++) xv[i] = xr[lane + i * 32];

        float best = -1e30f;
        int bsel = 0;
#pragma unroll
        for (int e = 0; e < E_NUM; e++) {
            const float* gw = sgw + e * H_DIM;
            float s = 0.f;
#pragma unroll
            for (int i = 0; i < 32; i++) s += xv[i] * gw[lane + i * 32];
#pragma unroll
            for (int o = 16; o > 0; o >>= 1) s += __shfl_xor_sync(0xffffffffu, s, o);
            if (s > best) { best = s; bsel = e; }
        }
        if (lane == 0) {
            g_sel[token] = bsel;
            g_rw[token] = 1.f / (1.f + expf(-best));
        }
    } else {
        const int N4 = (E_NUM * I_DIM * H_DIM) / 4;
        int i = (blockIdx.x - RT_B) * blockDim.x + threadIdx.x;
        int stride = (FUSE_B - RT_B) * blockDim.x;
        for (; i < N4; i += stride) {
            float4 a = ((const float4*)wg)[i];
            ((__half2*)g_wg)[i * 2]     = __floats2half2_rn(a.x, a.y);
            ((__half2*)g_wg)[i * 2 + 1] = __floats2half2_rn(a.z, a.w);
            float4 b = ((const float4*)wu)[i];
            ((__half2*)g_wu)[i * 2]     = __floats2half2_rn(b.x, b.y);
            ((__half2*)g_wu)[i * 2 + 1] = __floats2half2_rn(b.z, b.w);
            float4 c = ((const float4*)wd)[i];
            ((__half2*)g_wd)[i * 2]     = __floats2half2_rn(c.x, c.y);
            ((__half2*)g_wd)[i * 2 + 1] = __floats2half2_rn(c.z, c.w);
        }
    }
}

// ---------------- K2: count + prefix + assign (single block) -----------------
__global__ __launch_bounds__(1024) void route_finish_kernel() {
    __shared__ int scnt[E_NUM];
    __shared__ int sfill[E_NUM];
    int tid = threadIdx.x;
    if (tid < E_NUM) scnt[tid] = 0;
    __syncthreads();
    for (int i = tid; i < T_TOK; i += 1024) atomicAdd(&scnt[g_sel[i]], 1);
    __syncthreads();
    if (tid == 0) {
        int acc = 0;
        for (int e = 0; e < E_NUM; e++) {
            g_off[e] = acc;
            sfill[e] = acc;
            acc += scnt[e];
        }
        g_off[E_NUM] = acc;
    }
    __syncthreads();
    for (int i = tid; i < T_TOK; i += 1024) {
        int p = atomicAdd(&sfill[g_sel[i]], 1);
        g_tok[p] = i;
        g_pos[i] = p;
    }
}

// ---------------- K3: rw-scaled input scatter -> fp16 ------------------------
__global__ void copy_x_kernel(const float* __restrict__ x) {
    const int TOTAL = T_TOK * (H_DIM / 4);
    int i = blockIdx.x * blockDim.x + threadIdx.x;
    int stride = gridDim.x * blockDim.x;
    for (; i < TOTAL; i += stride) {
        int t = i >> 8;
        int j = i & 255;
        int p = g_pos[t];
        float rw = g_rw[t];
        float4 v = ((const float4*)(x + (size_t)t * H_DIM))[j];
        __half2 lo = __floats2half2_rn(v.x * rw, v.y * rw);
        __half2 hi = __floats2half2_rn(v.z * rw, v.w * rw);
        ((__half2*)(g_xs + (size_t)p * H_DIM))[j * 2]     = lo;
        ((__half2*)(g_xs + (size_t)p * H_DIM))[j * 2 + 1] = hi;
    }
}

// ---------------- K4: grouped GEMM1 fp16 (gate & up fused) + silu ------------
// Block tile 128(M) x 64(N), BK=64, 2-stage cp.async double buffer.
// 8 warps in 4x2 grid; warp tile 32x32, gate & up accumulators in registers.
#define SP 72                       /* smem row stride in halves */
#define G1_STG_H ((128 + 64 + 64) * SP)   /* 18432 halves = 36864 B */
__global__ __launch_bounds__(256) void gemm1_kernel() {
    extern __shared__ __half sm[];
    int e = blockIdx.z;
    int ps = g_off[e], pe = g_off[e + 1];
    int row0 = ps + blockIdx.y * 128;
    if (row0 >= pe) return;
    int i0 = blockIdx.x * 64;

    int tid = threadIdx.x;
    int wid = tid >> 5;
    int wm = wid >> 1, wn = wid & 1;

    unsigned sb = (unsigned)__cvta_generic_to_shared(sm);
    const __half* wgb = g_wg + ((size_t)e * I_DIM + i0) * H_DIM;
    const __half* wub = g_wu + ((size_t)e * I_DIM + i0) * H_DIM;

    wmma::fragment<wmma::accumulator, 16, 16, 16, float> cg[2][2], cu[2][2];
#pragma unroll
    for (int mm = 0; mm < 2; mm++)
#pragma unroll
        for (int nn = 0; nn < 2; nn++) {
            wmma::fill_fragment(cg[mm][nn], 0.f);
            wmma::fill_fragment(cu[mm][nn], 0.f);
        }

    auto issue = [&](int kt, int s) {
        int k0 = kt * 64;
        unsigned As = sb + s * G1_STG_H * 2;
        unsigned Wg = As + 128 * SP * 2;
        unsigned Wu = Wg + 64 * SP * 2;
#pragma unroll
        for (int it = 0; it < 4; it++) {                    // A: 128 x 64 halves
            int idx = tid + it * 256;
            int r = idx >> 3, c = idx & 7;
            int gr = row0 + r; if (gr > pe - 1) gr = pe - 1;
            cp16(As + (r * SP + c * 8) * 2, g_xs + (size_t)gr * H_DIM + k0 + c * 8);
        }
#pragma unroll
        for (int it = 0; it < 2; it++) {                    // Wg, Wu: 64 x 64
            int idx = tid + it * 256;
            int r = idx >> 3, c = idx & 7;
            cp16(Wg + (r * SP + c * 8) * 2, wgb + (size_t)r * H_DIM + k0 + c * 8);
            cp16(Wu + (r * SP + c * 8) * 2, wub + (size_t)r * H_DIM + k0 + c * 8);
        }
        cp_commit();
    };

    issue(0, 0);
    const int KT = H_DIM / 64;
    for (int kt = 0; kt < KT; kt++) {
        int s = kt & 1;
        if (kt + 1 < KT) { issue(kt + 1, s ^ 1); cp_wait<1>(); }
        else             { cp_wait<0>(); }
        __syncthreads();

        __half* As  = sm + s * G1_STG_H;
        __half* Wgs = As + 128 * SP;
        __half* Wus = Wgs + 64 * SP;
#pragma unroll
        for (int ks = 0; ks < 4; ks++) {
            wmma::fragment<wmma::matrix_a, 16, 16, 16, __half, wmma::row_major> a[2];
            wmma::fragment<wmma::matrix_b, 16, 16, 16, __half, wmma::col_major> bg[2], bu[2];
#pragma unroll
            for (int mm = 0; mm < 2; mm++)
                wmma::load_matrix_sync(a[mm], As + (wm * 32 + mm * 16) * SP + ks * 16, SP);
#pragma unroll
            for (int nn = 0; nn < 2; nn++) {
                wmma::load_matrix_sync(bg[nn], Wgs + (wn * 32 + nn * 16) * SP + ks * 16, SP);
                wmma::load_matrix_sync(bu[nn], Wus + (wn * 32 + nn * 16) * SP + ks * 16, SP);
            }
#pragma unroll
            for (int mm = 0; mm < 2; mm++)
#pragma unroll
                for (int nn = 0; nn < 2; nn++) {
                    wmma::mma_sync(cg[mm][nn], a[mm], bg[nn], cg[mm][nn]);
                    wmma::mma_sync(cu[mm][nn], a[mm], bu[nn], cu[mm][nn]);
                }
        }
        __syncthreads();
    }

    // SwiGLU in registers -> float smem -> fp16 g_mid
    float* Epi = (float*)sm;                     // 128 x 72 floats = 36864 B
#pragma unroll
    for (int mm = 0; mm < 2; mm++)
#pragma unroll
        for (int nn = 0; nn < 2; nn++) {
            wmma::fragment<wmma::accumulator, 16, 16, 16, float> t;
#pragma unroll
            for (int i = 0; i < t.num_elements; i++) {
                float g = cg[mm][nn].x[i];
                t.x[i] = cu[mm][nn].x[i] * g / (1.f + expf(-g));
            }
            wmma::store_matrix_sync(Epi + (wm * 32 + mm * 16) * SP + wn * 32 + nn * 16,
                                    t, SP, wmma::mem_row_major);
        }
    __syncthreads();

    for (int idx = tid; idx < 128 * 8; idx += 256) {     // 8 halves per item
        int r = idx >> 3, c8 = idx & 7;
        int p = row0 + r;
        if (p < pe) {
            const float* src = Epi + r * SP + c8 * 8;
            __half2 h[4];
#pragma unroll
            for (int q = 0; q < 4; q++) h[q] = __floats2half2_rn(src[q * 2], src[q * 2 + 1]);
            *(uint4*)(g_mid + (size_t)p * I_DIM + i0 + c8 * 8) = *(uint4*)h;
        }
    }
}

// ---------------- K5: grouped GEMM2 fp16 (down) + scatter to output ----------
// Block tile 128(M) x 128(N), BK=64, K=512, 2-stage pipeline.
// 8 warps in 2x4 grid; warp tile 64x32.
#define G2_STG_H ((128 + 128) * SP)              /* 18432 halves = 36864 B */
#define EPS 132                                  /* epilogue fp32 row stride */
__global__ __launch_bounds__(256) void gemm2_kernel(float* __restrict__ out) {
    extern __shared__ __half sm[];
    int e = blockIdx.z;
    int ps = g_off[e], pe = g_off[e + 1];
    int row0 = ps + blockIdx.y * 128;
    if (row0 >= pe) return;
    int n0 = blockIdx.x * 128;

    int tid = threadIdx.x;
    int wid = tid >> 5;
    int wm = wid >> 2, wn = wid & 3;             // 2x4 warp grid, tile 64x32

    unsigned sb = (unsigned)__cvta_generic_to_shared(sm);
    const __half* wdb = g_wd + ((size_t)e * H_DIM + n0) * I_DIM;

    wmma::fragment<wmma::accumulator, 16, 16, 16, float> c[4][2];
#pragma unroll
    for (int mm = 0; mm < 4; mm++)
#pragma unroll
        for (int nn = 0; nn < 2; nn++) wmma::fill_fragment(c[mm][nn], 0.f);

    auto issue = [&](int kt, int s) {
        int k0 = kt * 64;
        unsigned As = sb + s * G2_STG_H * 2;
        unsigned Ws = As + 128 * SP * 2;
#pragma unroll
        for (int it = 0; it < 4; it++) {                    // A: 128 x 64 halves
            int idx = tid + it * 256;
            int r = idx >> 3, cc = idx & 7;
            int gr = row0 + r; if (gr > pe - 1) gr = pe - 1;
            cp16(As + (r * SP + cc * 8) * 2, g_mid + (size_t)gr * I_DIM + k0 + cc * 8);
        }
#pragma unroll
        for (int it = 0; it < 4; it++) {                    // W: 128 x 64 halves
            int idx = tid + it * 256;
            int r = idx >> 3, cc = idx & 7;
            cp16(Ws + (r * SP + cc * 8) * 2, wdb + (size_t)r * I_DIM + k0 + cc * 8);
        }
        cp_commit();
    };

    issue(0, 0);
    const int KT = I_DIM / 64;
    for (int kt = 0; kt < KT; kt++) {
        int s = kt & 1;
        if (kt + 1 < KT) { issue(kt + 1, s ^ 1); cp_wait<1>(); }
        else             { cp_wait<0>(); }
        __syncthreads();

        __half* As = sm + s * G2_STG_H;
        __half* Ws = As + 128 * SP;
#pragma unroll
        for (int ks = 0; ks < 4; ks++) {
            wmma::fragment<wmma::matrix_a, 16, 16, 16, __half, wmma::row_major> a[4];
            wmma::fragment<wmma::matrix_b, 16, 16, 16, __half, wmma::col_major> b[2];
#pragma unroll
            for (int mm = 0; mm < 4; mm++)
                wmma::load_matrix_sync(a[mm], As + (wm * 64 + mm * 16) * SP + ks * 16, SP);
#pragma unroll
            for (int nn = 0; nn < 2; nn++)
                wmma::load_matrix_sync(b[nn], Ws + (wn * 32 + nn * 16) * SP + ks * 16, SP);
#pragma unroll
            for (int mm = 0; mm < 4; mm++)
#pragma unroll
                for (int nn = 0; nn < 2; nn++)
                    wmma::mma_sync(c[mm][nn], a[mm], b[nn], c[mm][nn]);
        }
        __syncthreads();
    }

    float* Epi = (float*)sm;                     // 128 x 132 floats = 67584 B
#pragma unroll
    for (int mm = 0; mm < 4; mm++)
#pragma unroll
        for (int nn = 0; nn < 2; nn++)
            wmma::store_matrix_sync(Epi + (wm * 64 + mm * 16) * EPS + wn * 32 + nn * 16,
                                    c[mm][nn], EPS, wmma::mem_row_major);
    __syncthreads();

    for (int idx = tid; idx < 128 * 32; idx += 256) {    // float4 per item
        int r = idx >> 5, c4 = idx & 31;
        int p = row0 + r;
        if (p < pe) {
            int t = g_tok[p];
            float4 v = *(const float4*)(Epi + r * EPS + c4 * 4);
            *(float4*)(out + (size_t)t * H_DIM + n0 + c4 * 4) = v;
        }
    }
}

// ---------------- launch ------------------------------------------------------
extern "C" void kernel_launch(void* const* d_in, const int* in_sizes, int n_in,
                              void* d_out, int out_size) {
    const float* x      = (const float*)d_in[0];
    const float* gate_w = (const float*)d_in[1];
    const float* w_gate = (const float*)d_in[2];
    const float* w_up   = (const float*)d_in[3];
    const float* w_down = (const float*)d_in[4];
    float* out = (float*)d_out;

    const int SM1 = 2 * G1_STG_H * 2;   // 73728 B
    const int SM2 = 2 * G2_STG_H * 2;   // 73728 B (epilogue 67584 B fits)
    cudaFuncSetAttribute(gemm1_kernel, cudaFuncAttributeMaxDynamicSharedMemorySize, SM1);
    cudaFuncSetAttribute(gemm2_kernel, cudaFuncAttributeMaxDynamicSharedMemorySize, SM2);

    fused_router_prep_kernel<<<FUSE_B, 256>>>(x, gate_w, w_gate, w_up, w_down);
    route_finish_kernel<<<1, 1024>>>();
    copy_x_kernel<<<1024, 256>>>(x);
    gemm1_kernel<<<dim3(I_DIM / 64, T_TOK / 128, E_NUM), 256, SM1>>>();
    gemm2_kernel<<<dim3(H_DIM / 128, T_TOK / 128, E_NUM), 256, SM2>>>(out);
}